// round 1
// baseline (speedup 1.0000x reference)
#include <cuda_runtime.h>
#include <cstdint>
#include <math.h>

#define B_DIM 128
#define T_DIM 64
#define E_DIM 300
#define H_DIM 2048
#define NCOL 16          // H columns per CTA
#define KC 16            // K chunk staged in smem
#define PAD 20           // smem k-stride (conflict-free: (20r+k) distinct mod 32)
#define NTHREADS 256

// dynamic smem layout (floats):
//  [0,2560)      sA_hi   (128 x PAD)
//  [2560,5120)   sA_lo
//  [5120,6400)   sW_hi   (64 x PAD)
//  [6400,7680)   sW_lo
//  [7680,7808)   s_idx (int)
//  gates alias [0, 8192)  (4 x 128 x 16)
#define SMEM_FLOATS 8192
#define SMEM_BYTES (SMEM_FLOATS * 4)

__device__ float g_h[2][B_DIM * H_DIM];
__device__ float g_c[B_DIM * H_DIM];

__device__ __forceinline__ uint32_t f2u(float x) { return __float_as_uint(x); }

__device__ __forceinline__ float tf32r(float x) {
    uint32_t r;
    asm("cvt.rna.tf32.f32 %0, %1;" : "=r"(r) : "f"(x));
    return __uint_as_float(r);
}

__device__ __forceinline__ void mma8(float c[4],
                                     uint32_t a0, uint32_t a1, uint32_t a2, uint32_t a3,
                                     uint32_t b0, uint32_t b1) {
    asm volatile(
        "mma.sync.aligned.m16n8k8.row.col.f32.tf32.tf32.f32 "
        "{%0,%1,%2,%3}, {%4,%5,%6,%7}, {%8,%9}, {%0,%1,%2,%3};"
        : "+f"(c[0]), "+f"(c[1]), "+f"(c[2]), "+f"(c[3])
        : "r"(a0), "r"(a1), "r"(a2), "r"(a3), "r"(b0), "r"(b1));
}

__global__ void init_state_kernel() {
    int i = blockIdx.x * blockDim.x + threadIdx.x;
    if (i < B_DIM * H_DIM) {
        g_h[0][i] = 0.f;
        g_c[i] = 0.f;
    }
}

__device__ __forceinline__ void split4(float4 v, float4& hv, float4& lv) {
    hv.x = tf32r(v.x); lv.x = tf32r(v.x - hv.x);
    hv.y = tf32r(v.y); lv.y = tf32r(v.y - hv.y);
    hv.z = tf32r(v.z); lv.z = tf32r(v.z - hv.z);
    hv.w = tf32r(v.w); lv.w = tf32r(v.w - hv.w);
}

__device__ __forceinline__ void do_mma(const float* __restrict__ sA_hi,
                                       const float* __restrict__ sA_lo,
                                       const float* __restrict__ sW_hi,
                                       const float* __restrict__ sW_lo,
                                       float acc[4][2][4],
                                       int warp_m, int warp_g, int ly, int lx) {
#pragma unroll
    for (int kk = 0; kk < KC; kk += 8) {
        uint32_t bh[2][2], bl[2][2];
#pragma unroll
        for (int nt = 0; nt < 2; nt++) {
            int br = (warp_g * 16 + nt * 8 + ly) * PAD + kk + lx;
            bh[nt][0] = f2u(sW_hi[br]);
            bh[nt][1] = f2u(sW_hi[br + 4]);
            bl[nt][0] = f2u(sW_lo[br]);
            bl[nt][1] = f2u(sW_lo[br + 4]);
        }
#pragma unroll
        for (int mt = 0; mt < 4; mt++) {
            int ar = (warp_m * 64 + mt * 16 + ly) * PAD + kk + lx;
            uint32_t ah0 = f2u(sA_hi[ar]);
            uint32_t ah1 = f2u(sA_hi[ar + 8 * PAD]);
            uint32_t ah2 = f2u(sA_hi[ar + 4]);
            uint32_t ah3 = f2u(sA_hi[ar + 8 * PAD + 4]);
            uint32_t al0 = f2u(sA_lo[ar]);
            uint32_t al1 = f2u(sA_lo[ar + 8 * PAD]);
            uint32_t al2 = f2u(sA_lo[ar + 4]);
            uint32_t al3 = f2u(sA_lo[ar + 8 * PAD + 4]);
#pragma unroll
            for (int nt = 0; nt < 2; nt++) {
                mma8(acc[mt][nt], ah0, ah1, ah2, ah3, bh[nt][0], bh[nt][1]);
                mma8(acc[mt][nt], ah0, ah1, ah2, ah3, bl[nt][0], bl[nt][1]);
                mma8(acc[mt][nt], al0, al1, al2, al3, bh[nt][0], bh[nt][1]);
            }
        }
    }
}

__global__ __launch_bounds__(NTHREADS) void lstm_step_kernel(
    int t,
    const float* __restrict__ h_in, float* __restrict__ h_out,
    const int* __restrict__ input, const float* __restrict__ embed,
    const float* __restrict__ w_ih, const float* __restrict__ w_hh,
    const float* __restrict__ b_ih, const float* __restrict__ b_hh) {
    extern __shared__ float sm[];
    float* sA_hi = sm;
    float* sA_lo = sm + 2560;
    float* sW_hi = sm + 5120;
    float* sW_lo = sm + 6400;
    int* s_idx = (int*)(sm + 7680);
    float* sg = sm;  // gates alias (used only after final sync)

    const int tid = threadIdx.x;
    const int lane = tid & 31;
    const int wid = tid >> 5;
    const int warp_m = wid & 1;   // M half (64 rows each)
    const int warp_g = wid >> 1;  // gate index 0..3 (= N quarter)
    const int ly = lane >> 2;
    const int lx = lane & 3;
    const int j0 = blockIdx.x * NCOL;

    if (tid < B_DIM) s_idx[tid] = input[tid * T_DIM + t];

    // accumulators init with biases (per output column)
    float acc[4][2][4];
#pragma unroll
    for (int nt = 0; nt < 2; nt++) {
        int n0 = warp_g * H_DIM + j0 + nt * 8 + 2 * lx;
        float bias0 = b_ih[n0] + b_hh[n0];
        float bias1 = b_ih[n0 + 1] + b_hh[n0 + 1];
#pragma unroll
        for (int mt = 0; mt < 4; mt++) {
            acc[mt][nt][0] = bias0;
            acc[mt][nt][1] = bias1;
            acc[mt][nt][2] = bias0;
            acc[mt][nt][3] = bias1;
        }
    }

    // ---- Phase 0: K over H_DIM, A = h_in, W = w_hh ----
#pragma unroll 1
    for (int k0 = 0; k0 < H_DIM; k0 += KC) {
#pragma unroll
        for (int idx = tid; idx < (B_DIM * KC / 4); idx += NTHREADS) {
            int row = idx >> 2;
            int kq = (idx & 3) << 2;
            float4 v = *reinterpret_cast<const float4*>(h_in + row * H_DIM + k0 + kq);
            float4 hv, lv;
            split4(v, hv, lv);
            *reinterpret_cast<float4*>(sA_hi + row * PAD + kq) = hv;
            *reinterpret_cast<float4*>(sA_lo + row * PAD + kq) = lv;
        }
#pragma unroll
        for (int idx = tid; idx < (64 * KC / 4); idx += NTHREADS) {
            int row = idx >> 2;
            int kq = (idx & 3) << 2;
            int grow = (row >> 4) * H_DIM + j0 + (row & 15);
            float4 v = *reinterpret_cast<const float4*>(w_hh + grow * H_DIM + k0 + kq);
            float4 hv, lv;
            split4(v, hv, lv);
            *reinterpret_cast<float4*>(sW_hi + row * PAD + kq) = hv;
            *reinterpret_cast<float4*>(sW_lo + row * PAD + kq) = lv;
        }
        __syncthreads();
        do_mma(sA_hi, sA_lo, sW_hi, sW_lo, acc, warp_m, warp_g, ly, lx);
        __syncthreads();
    }

    // ---- Phase 1: K over E_DIM (padded to 304), A = embed gather, W = w_ih ----
#pragma unroll 1
    for (int k0 = 0; k0 < 304; k0 += KC) {
#pragma unroll
        for (int idx = tid; idx < (B_DIM * KC / 4); idx += NTHREADS) {
            int row = idx >> 2;
            int kq = (idx & 3) << 2;
            int kg = k0 + kq;
            float4 v = make_float4(0.f, 0.f, 0.f, 0.f);
            if (kg < E_DIM)
                v = *reinterpret_cast<const float4*>(embed + s_idx[row] * E_DIM + kg);
            float4 hv, lv;
            split4(v, hv, lv);
            *reinterpret_cast<float4*>(sA_hi + row * PAD + kq) = hv;
            *reinterpret_cast<float4*>(sA_lo + row * PAD + kq) = lv;
        }
#pragma unroll
        for (int idx = tid; idx < (64 * KC / 4); idx += NTHREADS) {
            int row = idx >> 2;
            int kq = (idx & 3) << 2;
            int kg = k0 + kq;
            int grow = (row >> 4) * H_DIM + j0 + (row & 15);
            float4 v = make_float4(0.f, 0.f, 0.f, 0.f);
            if (kg < E_DIM)
                v = *reinterpret_cast<const float4*>(w_ih + grow * E_DIM + kg);
            float4 hv, lv;
            split4(v, hv, lv);
            *reinterpret_cast<float4*>(sW_hi + row * PAD + kq) = hv;
            *reinterpret_cast<float4*>(sW_lo + row * PAD + kq) = lv;
        }
        __syncthreads();
        do_mma(sA_hi, sA_lo, sW_hi, sW_lo, acc, warp_m, warp_g, ly, lx);
        __syncthreads();
    }

    // ---- Epilogue: exchange gates through smem, apply LSTM cell ----
#pragma unroll
    for (int mt = 0; mt < 4; mt++) {
        int r0 = warp_m * 64 + mt * 16 + ly;
#pragma unroll
        for (int nt = 0; nt < 2; nt++) {
            int c0 = nt * 8 + 2 * lx;
            int base = warp_g * (B_DIM * NCOL) + r0 * NCOL + c0;
            sg[base] = acc[mt][nt][0];
            sg[base + 1] = acc[mt][nt][1];
            sg[base + 8 * NCOL] = acc[mt][nt][2];
            sg[base + 8 * NCOL + 1] = acc[mt][nt][3];
        }
    }
    __syncthreads();

#pragma unroll
    for (int i = 0; i < 8; i++) {
        int r = (tid >> 4) + 16 * i;
        int c = tid & 15;
        int gi = r * NCOL + c;
        float xi = sg[gi];
        float xf = sg[B_DIM * NCOL + gi];
        float xg = sg[2 * B_DIM * NCOL + gi];
        float xo = sg[3 * B_DIM * NCOL + gi];
        float ig = 1.f / (1.f + expf(-xi));
        float fg = 1.f / (1.f + expf(-xf));
        float gg = tanhf(xg);
        float og = 1.f / (1.f + expf(-xo));
        int off = r * H_DIM + j0 + c;
        float cn = fg * g_c[off] + ig * gg;
        g_c[off] = cn;
        h_out[off] = og * tanhf(cn);
    }
}

extern "C" void kernel_launch(void* const* d_in, const int* in_sizes, int n_in,
                              void* d_out, int out_size) {
    const int* input = (const int*)d_in[0];
    const float* embed = (const float*)d_in[1];
    const float* w_ih = (const float*)d_in[2];
    const float* w_hh = (const float*)d_in[3];
    const float* b_ih = (const float*)d_in[4];
    const float* b_hh = (const float*)d_in[5];
    float* out = (float*)d_out;

    float* hbase = nullptr;
    cudaGetSymbolAddress((void**)&hbase, g_h);

    init_state_kernel<<<(B_DIM * H_DIM + 255) / 256, 256>>>();

    for (int t = 0; t < T_DIM; t++) {
        const float* hin = hbase + (size_t)(t & 1) * (B_DIM * H_DIM);
        float* hout = (t == T_DIM - 1) ? out
                                       : hbase + (size_t)((t + 1) & 1) * (B_DIM * H_DIM);
        lstm_step_kernel<<<H_DIM / NCOL, NTHREADS, SMEM_BYTES>>>(
            t, hin, hout, input, embed, w_ih, w_hh, b_ih, b_hh);
    }
}

// round 4
// speedup vs baseline: 6.1162x; 6.1162x over previous
#include <cuda_runtime.h>
#include <cuda_bf16.h>
#include <cstdint>
#include <math.h>

// ---------------- problem dims ----------------
#define B_DIM 128
#define T_DIM 64
#define E_DIM 300
#define H_DIM 2048
#define NCTA  128          // each CTA owns 16 H-cols x 4 gates = N=64 output cols
#define NKT   37           // K tiles of 64: 32 (h part) + 5 (x part, 320 padded)
#define KTH   32
#define A_TILE 32768       // [hi 16K][lo 16K], 128 rows x 128B, SW128
#define W_TILE 16384       // [hi 8K][lo 8K],   64 rows x 128B, SW128
#define STAGE_BYTES (A_TILE + W_TILE)   // 49152
#define NS 4
#define SC_OFF (NS * STAGE_BYTES)       // 196608
#define SMEM_TOTAL (SC_OFF + 512)

// ---------------- device scratch ----------------
__device__ __align__(128) uint8_t g_W[(size_t)NCTA * NKT * W_TILE];   // ~75.8 MB
__device__ __align__(128) uint8_t g_A[2][(size_t)KTH * A_TILE];       // 2 x 1 MB
__device__ __align__(128) uint8_t g_X[T_DIM][(size_t)5 * A_TILE];     // 10 MB
__device__ float g_c[B_DIM * H_DIM];
__device__ float g_bsum[4 * H_DIM];

// ---------------- PTX helpers ----------------
__device__ __forceinline__ uint32_t s2u(const void* p) {
    uint32_t a;
    asm("{ .reg .u64 t; cvta.to.shared.u64 t, %1; cvt.u32.u64 %0, t; }"
        : "=r"(a) : "l"(p));
    return a;
}

__device__ __forceinline__ void mbar_init(uint32_t a, uint32_t cnt) {
    asm volatile("mbarrier.init.shared.b64 [%0], %1;" :: "r"(a), "r"(cnt) : "memory");
}
__device__ __forceinline__ void mbar_arrive(uint32_t a) {
    asm volatile("mbarrier.arrive.shared.b64 _, [%0];" :: "r"(a) : "memory");
}
__device__ __forceinline__ void mbar_expect_tx(uint32_t a, uint32_t bytes) {
    asm volatile("mbarrier.arrive.expect_tx.shared.b64 _, [%0], %1;"
                 :: "r"(a), "r"(bytes) : "memory");
}
__device__ __forceinline__ void mbar_wait(uint32_t a, uint32_t par) {
    asm volatile(
        "{\n\t.reg .pred P;\n\t"
        "W%=:\n\t"
        "mbarrier.try_wait.parity.acquire.cta.shared::cta.b64 P, [%0], %1, 0x989680;\n\t"
        "@P bra D%=;\n\t"
        "bra W%=;\n\t"
        "D%=:\n\t}" :: "r"(a), "r"(par) : "memory");
}

__device__ __forceinline__ void bulk_g2s(uint32_t dst, const void* src,
                                         uint32_t bytes, uint32_t mbar) {
    asm volatile(
        "cp.async.bulk.shared::cluster.global.mbarrier::complete_tx::bytes "
        "[%0], [%1], %2, [%3];"
        :: "r"(dst), "l"(src), "r"(bytes), "r"(mbar) : "memory");
}

__device__ __forceinline__ void ldsm4(uint32_t a[4], uint32_t addr) {
    asm volatile("ldmatrix.sync.aligned.m8n8.x4.shared.b16 {%0,%1,%2,%3}, [%4];"
                 : "=r"(a[0]), "=r"(a[1]), "=r"(a[2]), "=r"(a[3]) : "r"(addr));
}

__device__ __forceinline__ void mma16816(float c[4], const uint32_t a[4],
                                         uint32_t b0, uint32_t b1) {
    asm volatile(
        "mma.sync.aligned.m16n8k16.row.col.f32.bf16.bf16.f32 "
        "{%0,%1,%2,%3}, {%4,%5,%6,%7}, {%8,%9}, {%0,%1,%2,%3};"
        : "+f"(c[0]), "+f"(c[1]), "+f"(c[2]), "+f"(c[3])
        : "r"(a[0]), "r"(a[1]), "r"(a[2]), "r"(a[3]), "r"(b0), "r"(b1));
}

__device__ __forceinline__ uint32_t swz(uint32_t off) {
    return off ^ ((off >> 3) & 0x70);
}

// ---------------- prep kernels ----------------
__global__ void prep_W(const float* __restrict__ w_ih,
                       const float* __restrict__ w_hh) {
    int j = blockIdx.x / NKT;
    int kt = blockIdx.x % NKT;
    uint8_t* base = g_W + ((size_t)(j * NKT + kt)) * W_TILE;
    for (int idx = threadIdx.x; idx < 64 * 64; idx += blockDim.x) {
        int r = idx >> 6, c = idx & 63;
        int g = r >> 4;
        int wr = g * H_DIM + j * 16 + (r & 15);
        float v = 0.f;
        if (kt < KTH) {
            v = w_hh[(size_t)wr * H_DIM + kt * 64 + c];
        } else {
            int ke = (kt - KTH) * 64 + c;
            if (ke < E_DIM) v = w_ih[(size_t)wr * E_DIM + ke];
        }
        __nv_bfloat16 hi = __float2bfloat16(v);
        __nv_bfloat16 lo = __float2bfloat16(v - __bfloat162float(hi));
        uint32_t sw = swz((uint32_t)(r * 128 + c * 2));
        *(__nv_bfloat16*)(base + sw) = hi;
        *(__nv_bfloat16*)(base + 8192 + sw) = lo;
    }
}

__global__ void prep_X(const int* __restrict__ input,
                       const float* __restrict__ embed) {
    int t = blockIdx.x / 5;
    int kt = blockIdx.x % 5;
    uint8_t* base = g_X[t] + (size_t)kt * A_TILE;
    for (int idx = threadIdx.x; idx < 128 * 64; idx += blockDim.x) {
        int row = idx >> 6, c = idx & 63;
        int ke = kt * 64 + c;
        float v = 0.f;
        if (ke < E_DIM) {
            int tok = input[row * T_DIM + t];
            v = embed[(size_t)tok * E_DIM + ke];
        }
        __nv_bfloat16 hi = __float2bfloat16(v);
        __nv_bfloat16 lo = __float2bfloat16(v - __bfloat162float(hi));
        uint32_t sw = swz((uint32_t)(row * 128 + c * 2));
        *(__nv_bfloat16*)(base + sw) = hi;
        *(__nv_bfloat16*)(base + 16384 + sw) = lo;
    }
}

__global__ void prep_init(const float* __restrict__ b_ih,
                          const float* __restrict__ b_hh) {
    int i = blockIdx.x * blockDim.x + threadIdx.x;
    if (i < 262144) {
        ((uint32_t*)g_A[0])[i] = 0u;   // h(0) bf16 tiles = 0
        g_c[i] = 0.f;
    }
    if (i < 4 * H_DIM) g_bsum[i] = b_ih[i] + b_hh[i];
}

// ---------------- step kernel ----------------
__global__ __launch_bounds__(256, 1) void lstm_step(int t, float* __restrict__ out) {
    extern __shared__ __align__(1024) uint8_t smem[];
    const uint32_t sbase = s2u(smem);
    const int tid = threadIdx.x;
    const int lane = tid & 31;
    const int wid = tid >> 5;
    const int warp_m = wid & 3;   // m0 = warp_m*32
    const int warp_n = wid >> 2;  // n0 = warp_n*32
    const int j0 = blockIdx.x * 16;

    const uint32_t full0 = sbase + SC_OFF;        // full[4]
    const uint32_t done0 = sbase + SC_OFF + 32;   // done[4], count=8
    float* sb = (float*)(smem + SC_OFF + 64);

    if (tid == 0) {
        for (int s = 0; s < NS; s++) {
            mbar_init(full0 + 8 * s, 1);
            mbar_init(done0 + 8 * s, 8);
        }
    }
    if (tid >= 64 && tid < 128) {
        int i = tid - 64;
        sb[i] = g_bsum[(i >> 4) * H_DIM + j0 + (i & 15)];
    }
    __syncthreads();

    const uint8_t* abuf = g_A[t & 1];
    const uint8_t* xbuf = g_X[t];
    const uint8_t* wbuf = g_W + (size_t)blockIdx.x * NKT * W_TILE;

    // producer fill helper (tid 0 only)
    auto fill = [&](int c) {
        uint32_t stg = sbase + (uint32_t)(c & 3) * STAGE_BYTES;
        uint32_t fb = full0 + 8 * (c & 3);
        mbar_expect_tx(fb, STAGE_BYTES);
        const uint8_t* asrc = (c < KTH) ? (abuf + (size_t)c * A_TILE)
                                        : (xbuf + (size_t)(c - KTH) * A_TILE);
        bulk_g2s(stg, asrc, A_TILE, fb);
        bulk_g2s(stg + A_TILE, wbuf + (size_t)c * W_TILE, W_TILE, fb);
    };

    if (tid == 0) {
        fill(0); fill(1); fill(2); fill(3);
    }

    // per-lane ldmatrix offset components
    const int r8 = lane & 7;
    const int ii = lane >> 3;
    const int a_row = warp_m * 32 + (ii & 1) * 8 + r8;   // + mt*16
    const int a_cb = (ii >> 1) * 16;                     // + kt*32
    const int w_row = warp_n * 32 + (ii >> 1) * 8 + r8;  // + nh*16
    const int w_cb = (ii & 1) * 16;                      // + kt*32

    float acc[2][4][4];
#pragma unroll
    for (int mt = 0; mt < 2; mt++)
#pragma unroll
        for (int nt = 0; nt < 4; nt++)
#pragma unroll
            for (int q = 0; q < 4; q++) acc[mt][nt][q] = 0.f;

    for (int c = 0; c < NKT; c++) {
        int s = c & 3;
        uint32_t stg = sbase + (uint32_t)s * STAGE_BYTES;
        mbar_wait(full0 + 8 * s, (c >> 2) & 1);
#pragma unroll
        for (int kt = 0; kt < 4; kt++) {
            uint32_t aH[2][4], aL[2][4], wH[2][4], wL[2][4];
#pragma unroll
            for (int mt = 0; mt < 2; mt++) {
                uint32_t off = (uint32_t)((a_row + mt * 16) * 128 + a_cb + kt * 32);
                uint32_t sw = swz(off);
                ldsm4(aH[mt], stg + sw);
                ldsm4(aL[mt], stg + 16384 + sw);
            }
#pragma unroll
            for (int nh = 0; nh < 2; nh++) {
                uint32_t off = (uint32_t)((w_row + nh * 16) * 128 + w_cb + kt * 32);
                uint32_t sw = swz(off);
                ldsm4(wH[nh], stg + 32768 + sw);
                ldsm4(wL[nh], stg + 40960 + sw);
            }
#pragma unroll
            for (int mt = 0; mt < 2; mt++) {
#pragma unroll
                for (int nh = 0; nh < 2; nh++) {
#pragma unroll
                    for (int p = 0; p < 2; p++) {
                        float* d = acc[mt][nh * 2 + p];
                        mma16816(d, aH[mt], wH[nh][2 * p], wH[nh][2 * p + 1]);
                        mma16816(d, aL[mt], wH[nh][2 * p], wH[nh][2 * p + 1]);
                        mma16816(d, aH[mt], wL[nh][2 * p], wL[nh][2 * p + 1]);
                    }
                }
            }
        }
        if (lane == 0) mbar_arrive(done0 + 8 * s);
        if (tid == 0 && c + 4 < NKT) {
            mbar_wait(done0 + 8 * s, (c >> 2) & 1);
            fill(c + 4);
        }
    }
    __syncthreads();

    // gates to smem (reuse stage area), stride 68 to dodge bank conflicts
    float* sg = (float*)smem;
#pragma unroll
    for (int mt = 0; mt < 2; mt++) {
        int mrow = warp_m * 32 + mt * 16 + (lane >> 2);
#pragma unroll
        for (int nt = 0; nt < 4; nt++) {
            int ncol = warp_n * 32 + nt * 8 + (lane & 3) * 2;
            sg[mrow * 68 + ncol] = acc[mt][nt][0];
            sg[mrow * 68 + ncol + 1] = acc[mt][nt][1];
            sg[(mrow + 8) * 68 + ncol] = acc[mt][nt][2];
            sg[(mrow + 8) * 68 + ncol + 1] = acc[mt][nt][3];
        }
    }
    __syncthreads();

    // LSTM cell: thread handles (m, cc) pairs
    const int ktile = j0 >> 6;
    const int cbase = j0 & 63;
    uint8_t* adst = g_A[(t + 1) & 1] + (size_t)ktile * A_TILE;
#pragma unroll
    for (int i = 0; i < 8; i++) {
        int m = (tid >> 4) + i * 16;
        int cc = tid & 15;
        int gi = m * 68 + cc;
        float xi = sg[gi] + sb[cc];
        float xf = sg[gi + 16] + sb[16 + cc];
        float xg = sg[gi + 32] + sb[32 + cc];
        float xo = sg[gi + 48] + sb[48 + cc];
        float ig = 1.f / (1.f + __expf(-xi));
        float fg = 1.f / (1.f + __expf(-xf));
        float gg = 2.f / (1.f + __expf(-2.f * xg)) - 1.f;
        float og = 1.f / (1.f + __expf(-xo));
        int co = m * H_DIM + j0 + cc;
        float cn = fg * g_c[co] + ig * gg;
        g_c[co] = cn;
        float hv = og * (2.f / (1.f + __expf(-2.f * cn)) - 1.f);
        if (t < T_DIM - 1) {
            __nv_bfloat16 hi = __float2bfloat16(hv);
            __nv_bfloat16 lo = __float2bfloat16(hv - __bfloat162float(hi));
            uint32_t sw = swz((uint32_t)(m * 128 + (cbase + cc) * 2));
            *(__nv_bfloat16*)(adst + sw) = hi;
            *(__nv_bfloat16*)(adst + 16384 + sw) = lo;
        } else {
            out[m * H_DIM + j0 + cc] = hv;
        }
    }
}

// ---------------- host ----------------
extern "C" void kernel_launch(void* const* d_in, const int* in_sizes, int n_in,
                              void* d_out, int out_size) {
    const int* input = (const int*)d_in[0];
    const float* embed = (const float*)d_in[1];
    const float* w_ih = (const float*)d_in[2];
    const float* w_hh = (const float*)d_in[3];
    const float* b_ih = (const float*)d_in[4];
    const float* b_hh = (const float*)d_in[5];
    float* out = (float*)d_out;

    cudaFuncSetAttribute(lstm_step, cudaFuncAttributeMaxDynamicSharedMemorySize,
                         SMEM_TOTAL);

    prep_W<<<NCTA * NKT, 256>>>(w_ih, w_hh);
    prep_X<<<T_DIM * 5, 256>>>(input, embed);
    prep_init<<<1024, 256>>>(b_ih, b_hh);

    for (int t = 0; t < T_DIM; t++) {
        lstm_step<<<NCTA, 256, SMEM_TOTAL>>>(t, out);
    }
}

// round 7
// speedup vs baseline: 7.8096x; 1.2769x over previous
#include <cuda_runtime.h>
#include <cuda_fp16.h>
#include <cstdint>
#include <math.h>

// ---------------- problem dims ----------------
#define B_DIM 128
#define T_DIM 64
#define E_DIM 300
#define H_DIM 2048
#define NCTA  128          // each CTA owns 16 H-cols x 4 gates = N=64 output cols
#define NKT   37           // K tiles of 64: 32 (h part) + 5 (x part, 320 padded)
#define KTH   32
#define A_TILE 16384       // A hi only: 128 rows x 128B, SW128
#define W_TILE 16384       // [hi 8K][lo 8K], 64 rows x 128B, SW128
#define STAGE_BYTES (A_TILE + W_TILE)   // 32768
#define NS 4
#define SC_OFF (NS * STAGE_BYTES)       // 131072
#define SMEM_TOTAL (SC_OFF + 512)

// ---------------- device scratch ----------------
__device__ __align__(128) uint8_t g_W[(size_t)NCTA * NKT * W_TILE];   // ~75.8 MB
__device__ __align__(128) uint8_t g_A[2][(size_t)KTH * A_TILE];       // 2 x 512 KB
__device__ __align__(128) uint8_t g_X[T_DIM][(size_t)5 * A_TILE];     // 5 MB
__device__ float g_c[B_DIM * H_DIM];
__device__ float g_bsum[4 * H_DIM];

// ---------------- PTX helpers ----------------
__device__ __forceinline__ uint32_t s2u(const void* p) {
    uint32_t a;
    asm("{ .reg .u64 t; cvta.to.shared.u64 t, %1; cvt.u32.u64 %0, t; }"
        : "=r"(a) : "l"(p));
    return a;
}

__device__ __forceinline__ void mbar_init(uint32_t a, uint32_t cnt) {
    asm volatile("mbarrier.init.shared.b64 [%0], %1;" :: "r"(a), "r"(cnt) : "memory");
}
__device__ __forceinline__ void mbar_arrive(uint32_t a) {
    asm volatile("mbarrier.arrive.shared.b64 _, [%0];" :: "r"(a) : "memory");
}
__device__ __forceinline__ void mbar_expect_tx(uint32_t a, uint32_t bytes) {
    asm volatile("mbarrier.arrive.expect_tx.shared.b64 _, [%0], %1;"
                 :: "r"(a), "r"(bytes) : "memory");
}
__device__ __forceinline__ void mbar_wait(uint32_t a, uint32_t par) {
    asm volatile(
        "{\n\t.reg .pred P;\n\t"
        "W%=:\n\t"
        "mbarrier.try_wait.parity.acquire.cta.shared::cta.b64 P, [%0], %1, 0x989680;\n\t"
        "@P bra D%=;\n\t"
        "bra W%=;\n\t"
        "D%=:\n\t}" :: "r"(a), "r"(par) : "memory");
}

__device__ __forceinline__ void bulk_g2s(uint32_t dst, const void* src,
                                         uint32_t bytes, uint32_t mbar) {
    asm volatile(
        "cp.async.bulk.shared::cluster.global.mbarrier::complete_tx::bytes "
        "[%0], [%1], %2, [%3];"
        :: "r"(dst), "l"(src), "r"(bytes), "r"(mbar) : "memory");
}

__device__ __forceinline__ void ldsm4(uint32_t a[4], uint32_t addr) {
    asm volatile("ldmatrix.sync.aligned.m8n8.x4.shared.b16 {%0,%1,%2,%3}, [%4];"
                 : "=r"(a[0]), "=r"(a[1]), "=r"(a[2]), "=r"(a[3]) : "r"(addr));
}

__device__ __forceinline__ void mma16816(float c[4], const uint32_t a[4],
                                         uint32_t b0, uint32_t b1) {
    asm volatile(
        "mma.sync.aligned.m16n8k16.row.col.f32.f16.f16.f32 "
        "{%0,%1,%2,%3}, {%4,%5,%6,%7}, {%8,%9}, {%0,%1,%2,%3};"
        : "+f"(c[0]), "+f"(c[1]), "+f"(c[2]), "+f"(c[3])
        : "r"(a[0]), "r"(a[1]), "r"(a[2]), "r"(a[3]), "r"(b0), "r"(b1));
}

__device__ __forceinline__ uint32_t swz(uint32_t off) {
    return off ^ ((off >> 3) & 0x70);
}

// ---------------- prep kernels ----------------
// W tiles: 64 rows (gate g = r>>4, col j*16+(r&15)), 64 K-cols, fp16 hi + lo.
__global__ void prep_W(const float* __restrict__ w_ih,
                       const float* __restrict__ w_hh) {
    int j = blockIdx.x / NKT;
    int kt = blockIdx.x % NKT;
    uint8_t* base = g_W + ((size_t)(j * NKT + kt)) * W_TILE;
    for (int idx = threadIdx.x; idx < 64 * 64; idx += blockDim.x) {
        int r = idx >> 6, c = idx & 63;
        int g = r >> 4;
        int wr = g * H_DIM + j * 16 + (r & 15);
        float v = 0.f;
        if (kt < KTH) {
            v = w_hh[(size_t)wr * H_DIM + kt * 64 + c];
        } else {
            int ke = (kt - KTH) * 64 + c;
            if (ke < E_DIM) v = w_ih[(size_t)wr * E_DIM + ke];
        }
        __half hi = __float2half_rn(v);
        __half lo = __float2half_rn(v - __half2float(hi));
        uint32_t sw = swz((uint32_t)(r * 128 + c * 2));
        *(__half*)(base + sw) = hi;
        *(__half*)(base + 8192 + sw) = lo;
    }
}

// X tiles: 128 rows (batch) x 64 K-cols of embed gather, fp16 hi only.
__global__ void prep_X(const int* __restrict__ input,
                       const float* __restrict__ embed) {
    int t = blockIdx.x / 5;
    int kt = blockIdx.x % 5;
    uint8_t* base = g_X[t] + (size_t)kt * A_TILE;
    for (int idx = threadIdx.x; idx < 128 * 64; idx += blockDim.x) {
        int row = idx >> 6, c = idx & 63;
        int ke = kt * 64 + c;
        float v = 0.f;
        if (ke < E_DIM) {
            int tok = input[row * T_DIM + t];
            v = embed[(size_t)tok * E_DIM + ke];
        }
        uint32_t sw = swz((uint32_t)(row * 128 + c * 2));
        *(__half*)(base + sw) = __float2half_rn(v);
    }
}

__global__ void prep_init(const float* __restrict__ b_ih,
                          const float* __restrict__ b_hh) {
    int i = blockIdx.x * blockDim.x + threadIdx.x;
    if (i < 131072) ((uint32_t*)g_A[0])[i] = 0u;   // h(0) fp16 tiles = 0
    if (i < 262144) g_c[i] = 0.f;
    if (i < 4 * H_DIM) g_bsum[i] = b_ih[i] + b_hh[i];
}

// ---------------- step kernel ----------------
__global__ __launch_bounds__(256, 1) void lstm_step(int t, float* __restrict__ out) {
    extern __shared__ __align__(1024) uint8_t smem[];
    const uint32_t sbase = s2u(smem);
    const int tid = threadIdx.x;
    const int lane = tid & 31;
    const int wid = tid >> 5;
    const int warp_m = wid & 3;   // m0 = warp_m*32
    const int warp_n = wid >> 2;  // n0 = warp_n*32
    const int j0 = blockIdx.x * 16;

    const uint32_t full0 = sbase + SC_OFF;        // full[4]
    const uint32_t done0 = sbase + SC_OFF + 32;   // done[4], count=8
    float* sb = (float*)(smem + SC_OFF + 64);

    if (tid == 0) {
        for (int s = 0; s < NS; s++) {
            mbar_init(full0 + 8 * s, 1);
            mbar_init(done0 + 8 * s, 8);
        }
    }
    if (tid >= 64 && tid < 128) {
        int i = tid - 64;
        sb[i] = g_bsum[(i >> 4) * H_DIM + j0 + (i & 15)];
    }
    __syncthreads();

    const uint8_t* abuf = g_A[t & 1];
    const uint8_t* xbuf = g_X[t];
    const uint8_t* wbuf = g_W + (size_t)blockIdx.x * NKT * W_TILE;

    auto fill = [&](int c) {
        uint32_t stg = sbase + (uint32_t)(c & 3) * STAGE_BYTES;
        uint32_t fb = full0 + 8 * (c & 3);
        mbar_expect_tx(fb, STAGE_BYTES);
        const uint8_t* asrc = (c < KTH) ? (abuf + (size_t)c * A_TILE)
                                        : (xbuf + (size_t)(c - KTH) * A_TILE);
        bulk_g2s(stg, asrc, A_TILE, fb);
        bulk_g2s(stg + A_TILE, wbuf + (size_t)c * W_TILE, W_TILE, fb);
    };

    if (tid == 0) {
        fill(0); fill(1); fill(2); fill(3);
    }

    // per-lane ldmatrix offset components
    const int r8 = lane & 7;
    const int ii = lane >> 3;
    const int a_row = warp_m * 32 + (ii & 1) * 8 + r8;   // + mt*16
    const int a_cb = (ii >> 1) * 16;                     // + kt*32
    const int w_row = warp_n * 32 + (ii >> 1) * 8 + r8;  // + nh*16
    const int w_cb = (ii & 1) * 16;                      // + kt*32

    float acc[2][4][4];
#pragma unroll
    for (int mt = 0; mt < 2; mt++)
#pragma unroll
        for (int nt = 0; nt < 4; nt++)
#pragma unroll
            for (int q = 0; q < 4; q++) acc[mt][nt][q] = 0.f;

    for (int c = 0; c < NKT; c++) {
        int s = c & 3;
        uint32_t stg = sbase + (uint32_t)s * STAGE_BYTES;
        mbar_wait(full0 + 8 * s, (c >> 2) & 1);
#pragma unroll
        for (int kt = 0; kt < 4; kt++) {
            uint32_t aH[2][4], wH[2][4], wL[2][4];
#pragma unroll
            for (int mt = 0; mt < 2; mt++) {
                uint32_t sw = swz((uint32_t)((a_row + mt * 16) * 128 + a_cb + kt * 32));
                ldsm4(aH[mt], stg + sw);
            }
#pragma unroll
            for (int nh = 0; nh < 2; nh++) {
                uint32_t sw = swz((uint32_t)((w_row + nh * 16) * 128 + w_cb + kt * 32));
                ldsm4(wH[nh], stg + A_TILE + sw);
                ldsm4(wL[nh], stg + A_TILE + 8192 + sw);
            }
#pragma unroll
            for (int mt = 0; mt < 2; mt++) {
#pragma unroll
                for (int nh = 0; nh < 2; nh++) {
#pragma unroll
                    for (int p = 0; p < 2; p++) {
                        float* d = acc[mt][nh * 2 + p];
                        mma16816(d, aH[mt], wH[nh][2 * p], wH[nh][2 * p + 1]);
                        mma16816(d, aH[mt], wL[nh][2 * p], wL[nh][2 * p + 1]);
                    }
                }
            }
        }
        if (lane == 0) mbar_arrive(done0 + 8 * s);
        if (tid == 0 && c + 4 < NKT) {
            mbar_wait(done0 + 8 * s, (c >> 2) & 1);
            fill(c + 4);
        }
    }
    __syncthreads();

    // gates to smem (reuse stage area), stride 68 to dodge bank conflicts
    float* sg = (float*)smem;
#pragma unroll
    for (int mt = 0; mt < 2; mt++) {
        int mrow = warp_m * 32 + mt * 16 + (lane >> 2);
#pragma unroll
        for (int nt = 0; nt < 4; nt++) {
            int ncol = warp_n * 32 + nt * 8 + (lane & 3) * 2;
            sg[mrow * 68 + ncol] = acc[mt][nt][0];
            sg[mrow * 68 + ncol + 1] = acc[mt][nt][1];
            sg[(mrow + 8) * 68 + ncol] = acc[mt][nt][2];
            sg[(mrow + 8) * 68 + ncol + 1] = acc[mt][nt][3];
        }
    }
    __syncthreads();

    // LSTM cell: thread handles (m, cc) pairs
    const int ktile = j0 >> 6;
    const int cbase = j0 & 63;
    uint8_t* adst = g_A[(t + 1) & 1] + (size_t)ktile * A_TILE;
#pragma unroll
    for (int i = 0; i < 8; i++) {
        int m = (tid >> 4) + i * 16;
        int cc = tid & 15;
        int gi = m * 68 + cc;
        float xi = sg[gi] + sb[cc];
        float xf = sg[gi + 16] + sb[16 + cc];
        float xg = sg[gi + 32] + sb[32 + cc];
        float xo = sg[gi + 48] + sb[48 + cc];
        float ig = 1.f / (1.f + __expf(-xi));
        float fg = 1.f / (1.f + __expf(-xf));
        float gg = 2.f / (1.f + __expf(-2.f * xg)) - 1.f;
        float og = 1.f / (1.f + __expf(-xo));
        int co = m * H_DIM + j0 + cc;
        float cn = fg * g_c[co] + ig * gg;
        g_c[co] = cn;
        float hv = og * (2.f / (1.f + __expf(-2.f * cn)) - 1.f);
        if (t < T_DIM - 1) {
            uint32_t sw = swz((uint32_t)(m * 128 + (cbase + cc) * 2));
            *(__half*)(adst + sw) = __float2half_rn(hv);
        } else {
            out[m * H_DIM + j0 + cc] = hv;
        }
    }
}

// ---------------- host ----------------
extern "C" void kernel_launch(void* const* d_in, const int* in_sizes, int n_in,
                              void* d_out, int out_size) {
    const int* input = (const int*)d_in[0];
    const float* embed = (const float*)d_in[1];
    const float* w_ih = (const float*)d_in[2];
    const float* w_hh = (const float*)d_in[3];
    const float* b_ih = (const float*)d_in[4];
    const float* b_hh = (const float*)d_in[5];
    float* out = (float*)d_out;

    cudaFuncSetAttribute(lstm_step, cudaFuncAttributeMaxDynamicSharedMemorySize,
                         SMEM_TOTAL);

    prep_W<<<NCTA * NKT, 256>>>(w_ih, w_hh);
    prep_X<<<T_DIM * 5, 256>>>(input, embed);
    prep_init<<<1024, 256>>>(b_ih, b_hh);

    for (int t = 0; t < T_DIM; t++) {
        lstm_step<<<NCTA, 256, SMEM_TOTAL>>>(t, out);
    }
}

// round 8
// speedup vs baseline: 10.6233x; 1.3603x over previous
#include <cuda_runtime.h>
#include <cuda_fp16.h>
#include <cstdint>
#include <math.h>

// ---------------- problem dims ----------------
#define B_DIM 128
#define T_DIM 64
#define E_DIM 300
#define H_DIM 2048
#define NCTA  128          // each CTA owns 16 H-cols x 4 gates = N=64 output cols
#define NKT   37           // K tiles of 64: 32 (h part) + 5 (x part, 320 padded)
#define KTH   32
#define A_TILE 16384       // A hi only: 128 rows x 128B, SW128
#define W_TILE 8192        // W hi only: 64 rows x 128B, SW128
#define STAGE_BYTES (A_TILE + W_TILE)   // 24576
#define NS 8
#define SC_OFF (NS * STAGE_BYTES)       // 196608
#define SMEM_TOTAL (SC_OFF + 512)

// ---------------- device scratch ----------------
__device__ __align__(128) uint8_t g_W[(size_t)NCTA * NKT * W_TILE];   // ~37.9 MB
__device__ __align__(128) uint8_t g_A[2][(size_t)KTH * A_TILE];       // 2 x 512 KB
__device__ __align__(128) uint8_t g_X[T_DIM][(size_t)5 * A_TILE];     // 5 MB
__device__ float g_c[B_DIM * H_DIM];
__device__ float g_bsum[4 * H_DIM];

// ---------------- PTX helpers ----------------
__device__ __forceinline__ uint32_t s2u(const void* p) {
    uint32_t a;
    asm("{ .reg .u64 t; cvta.to.shared.u64 t, %1; cvt.u32.u64 %0, t; }"
        : "=r"(a) : "l"(p));
    return a;
}

__device__ __forceinline__ void mbar_init(uint32_t a, uint32_t cnt) {
    asm volatile("mbarrier.init.shared.b64 [%0], %1;" :: "r"(a), "r"(cnt) : "memory");
}
__device__ __forceinline__ void mbar_arrive(uint32_t a) {
    asm volatile("mbarrier.arrive.shared.b64 _, [%0];" :: "r"(a) : "memory");
}
__device__ __forceinline__ void mbar_expect_tx(uint32_t a, uint32_t bytes) {
    asm volatile("mbarrier.arrive.expect_tx.shared.b64 _, [%0], %1;"
                 :: "r"(a), "r"(bytes) : "memory");
}
__device__ __forceinline__ void mbar_wait(uint32_t a, uint32_t par) {
    asm volatile(
        "{\n\t.reg .pred P;\n\t"
        "W%=:\n\t"
        "mbarrier.try_wait.parity.acquire.cta.shared::cta.b64 P, [%0], %1, 0x989680;\n\t"
        "@P bra D%=;\n\t"
        "bra W%=;\n\t"
        "D%=:\n\t}" :: "r"(a), "r"(par) : "memory");
}

__device__ __forceinline__ void bulk_g2s(uint32_t dst, const void* src,
                                         uint32_t bytes, uint32_t mbar) {
    asm volatile(
        "cp.async.bulk.shared::cluster.global.mbarrier::complete_tx::bytes "
        "[%0], [%1], %2, [%3];"
        :: "r"(dst), "l"(src), "r"(bytes), "r"(mbar) : "memory");
}

__device__ __forceinline__ void ldsm4(uint32_t a[4], uint32_t addr) {
    asm volatile("ldmatrix.sync.aligned.m8n8.x4.shared.b16 {%0,%1,%2,%3}, [%4];"
                 : "=r"(a[0]), "=r"(a[1]), "=r"(a[2]), "=r"(a[3]) : "r"(addr));
}

__device__ __forceinline__ void mma16816(float c[4], const uint32_t a[4],
                                         uint32_t b0, uint32_t b1) {
    asm volatile(
        "mma.sync.aligned.m16n8k16.row.col.f32.f16.f16.f32 "
        "{%0,%1,%2,%3}, {%4,%5,%6,%7}, {%8,%9}, {%0,%1,%2,%3};"
        : "+f"(c[0]), "+f"(c[1]), "+f"(c[2]), "+f"(c[3])
        : "r"(a[0]), "r"(a[1]), "r"(a[2]), "r"(a[3]), "r"(b0), "r"(b1));
}

__device__ __forceinline__ uint32_t swz(uint32_t off) {
    return off ^ ((off >> 3) & 0x70);
}

// ---------------- prep kernels ----------------
// W tiles: 64 rows (gate g = r>>4, col j*16+(r&15)), 64 K-cols, fp16.
__global__ void prep_W(const float* __restrict__ w_ih,
                       const float* __restrict__ w_hh) {
    int j = blockIdx.x / NKT;
    int kt = blockIdx.x % NKT;
    uint8_t* base = g_W + ((size_t)(j * NKT + kt)) * W_TILE;
    for (int idx = threadIdx.x; idx < 64 * 64; idx += blockDim.x) {
        int r = idx >> 6, c = idx & 63;
        int g = r >> 4;
        int wr = g * H_DIM + j * 16 + (r & 15);
        float v = 0.f;
        if (kt < KTH) {
            v = w_hh[(size_t)wr * H_DIM + kt * 64 + c];
        } else {
            int ke = (kt - KTH) * 64 + c;
            if (ke < E_DIM) v = w_ih[(size_t)wr * E_DIM + ke];
        }
        uint32_t sw = swz((uint32_t)(r * 128 + c * 2));
        *(__half*)(base + sw) = __float2half_rn(v);
    }
}

// X tiles: 128 rows (batch) x 64 K-cols of embed gather, fp16.
__global__ void prep_X(const int* __restrict__ input,
                       const float* __restrict__ embed) {
    int t = blockIdx.x / 5;
    int kt = blockIdx.x % 5;
    uint8_t* base = g_X[t] + (size_t)kt * A_TILE;
    for (int idx = threadIdx.x; idx < 128 * 64; idx += blockDim.x) {
        int row = idx >> 6, c = idx & 63;
        int ke = kt * 64 + c;
        float v = 0.f;
        if (ke < E_DIM) {
            int tok = input[row * T_DIM + t];
            v = embed[(size_t)tok * E_DIM + ke];
        }
        uint32_t sw = swz((uint32_t)(row * 128 + c * 2));
        *(__half*)(base + sw) = __float2half_rn(v);
    }
}

__global__ void prep_init(const float* __restrict__ b_ih,
                          const float* __restrict__ b_hh) {
    int i = blockIdx.x * blockDim.x + threadIdx.x;
    if (i < 131072) ((uint32_t*)g_A[0])[i] = 0u;   // h(0) fp16 tiles = 0
    if (i < 262144) g_c[i] = 0.f;
    if (i < 4 * H_DIM) g_bsum[i] = b_ih[i] + b_hh[i];
}

// ---------------- step kernel ----------------
__global__ __launch_bounds__(256, 1) void lstm_step(int t, float* __restrict__ out) {
    extern __shared__ __align__(1024) uint8_t smem[];
    const uint32_t sbase = s2u(smem);
    const int tid = threadIdx.x;
    const int lane = tid & 31;
    const int wid = tid >> 5;
    const int warp_m = wid & 3;   // m0 = warp_m*32
    const int warp_n = wid >> 2;  // n0 = warp_n*32
    const int j0 = blockIdx.x * 16;

    const uint32_t full0 = sbase + SC_OFF;        // full[8]
    const uint32_t done0 = sbase + SC_OFF + 64;   // done[8], count=8
    float* sb = (float*)(smem + SC_OFF + 128);

    if (tid == 0) {
        for (int s = 0; s < NS; s++) {
            mbar_init(full0 + 8 * s, 1);
            mbar_init(done0 + 8 * s, 8);
        }
    }
    if (tid >= 64 && tid < 128) {
        int i = tid - 64;
        sb[i] = g_bsum[(i >> 4) * H_DIM + j0 + (i & 15)];
    }
    __syncthreads();

    const uint8_t* abuf = g_A[t & 1];
    const uint8_t* xbuf = g_X[t];
    const uint8_t* wbuf = g_W + (size_t)blockIdx.x * NKT * W_TILE;

    auto fill = [&](int c) {
        uint32_t stg = sbase + (uint32_t)(c & (NS - 1)) * STAGE_BYTES;
        uint32_t fb = full0 + 8 * (c & (NS - 1));
        mbar_expect_tx(fb, STAGE_BYTES);
        const uint8_t* asrc = (c < KTH) ? (abuf + (size_t)c * A_TILE)
                                        : (xbuf + (size_t)(c - KTH) * A_TILE);
        bulk_g2s(stg, asrc, A_TILE, fb);
        bulk_g2s(stg + A_TILE, wbuf + (size_t)c * W_TILE, W_TILE, fb);
    };

    if (tid == 0) {
#pragma unroll
        for (int c = 0; c < NS; c++) fill(c);
    }

    // per-lane ldmatrix offset components
    const int r8 = lane & 7;
    const int ii = lane >> 3;
    const int a_row = warp_m * 32 + (ii & 1) * 8 + r8;   // + mt*16
    const int a_cb = (ii >> 1) * 16;                     // + kt*32
    const int w_row = warp_n * 32 + (ii >> 1) * 8 + r8;  // + nh*16
    const int w_cb = (ii & 1) * 16;                      // + kt*32

    float acc[2][4][4];
#pragma unroll
    for (int mt = 0; mt < 2; mt++)
#pragma unroll
        for (int nt = 0; nt < 4; nt++)
#pragma unroll
            for (int q = 0; q < 4; q++) acc[mt][nt][q] = 0.f;

    for (int c = 0; c < NKT; c++) {
        int s = c & (NS - 1);
        uint32_t stg = sbase + (uint32_t)s * STAGE_BYTES;
        mbar_wait(full0 + 8 * s, (c >> 3) & 1);
#pragma unroll
        for (int kt = 0; kt < 4; kt++) {
            uint32_t aH[2][4], wH[2][4];
#pragma unroll
            for (int mt = 0; mt < 2; mt++) {
                uint32_t sw = swz((uint32_t)((a_row + mt * 16) * 128 + a_cb + kt * 32));
                ldsm4(aH[mt], stg + sw);
            }
#pragma unroll
            for (int nh = 0; nh < 2; nh++) {
                uint32_t sw = swz((uint32_t)((w_row + nh * 16) * 128 + w_cb + kt * 32));
                ldsm4(wH[nh], stg + A_TILE + sw);
            }
#pragma unroll
            for (int mt = 0; mt < 2; mt++) {
#pragma unroll
                for (int nh = 0; nh < 2; nh++) {
#pragma unroll
                    for (int p = 0; p < 2; p++) {
                        mma16816(acc[mt][nh * 2 + p], aH[mt],
                                 wH[nh][2 * p], wH[nh][2 * p + 1]);
                    }
                }
            }
        }
        if (lane == 0) mbar_arrive(done0 + 8 * s);
        if (tid == 0 && c + NS < NKT) {
            mbar_wait(done0 + 8 * s, (c >> 3) & 1);
            fill(c + NS);
        }
    }
    __syncthreads();

    // gates to smem (reuse stage area), stride 68 to dodge bank conflicts
    float* sg = (float*)smem;
#pragma unroll
    for (int mt = 0; mt < 2; mt++) {
        int mrow = warp_m * 32 + mt * 16 + (lane >> 2);
#pragma unroll
        for (int nt = 0; nt < 4; nt++) {
            int ncol = warp_n * 32 + nt * 8 + (lane & 3) * 2;
            sg[mrow * 68 + ncol] = acc[mt][nt][0];
            sg[mrow * 68 + ncol + 1] = acc[mt][nt][1];
            sg[(mrow + 8) * 68 + ncol] = acc[mt][nt][2];
            sg[(mrow + 8) * 68 + ncol + 1] = acc[mt][nt][3];
        }
    }
    __syncthreads();

    // LSTM cell: thread handles (m, cc) pairs
    const int ktile = j0 >> 6;
    const int cbase = j0 & 63;
    uint8_t* adst = g_A[(t + 1) & 1] + (size_t)ktile * A_TILE;
#pragma unroll
    for (int i = 0; i < 8; i++) {
        int m = (tid >> 4) + i * 16;
        int cc = tid & 15;
        int gi = m * 68 + cc;
        float xi = sg[gi] + sb[cc];
        float xf = sg[gi + 16] + sb[16 + cc];
        float xg = sg[gi + 32] + sb[32 + cc];
        float xo = sg[gi + 48] + sb[48 + cc];
        float ig = 1.f / (1.f + __expf(-xi));
        float fg = 1.f / (1.f + __expf(-xf));
        float gg = 2.f / (1.f + __expf(-2.f * xg)) - 1.f;
        float og = 1.f / (1.f + __expf(-xo));
        int co = m * H_DIM + j0 + cc;
        float cn = fg * g_c[co] + ig * gg;
        g_c[co] = cn;
        float hv = og * (2.f / (1.f + __expf(-2.f * cn)) - 1.f);
        if (t < T_DIM - 1) {
            uint32_t sw = swz((uint32_t)(m * 128 + (cbase + cc) * 2));
            *(__half*)(adst + sw) = __float2half_rn(hv);
        } else {
            out[m * H_DIM + j0 + cc] = hv;
        }
    }
}

// ---------------- host ----------------
extern "C" void kernel_launch(void* const* d_in, const int* in_sizes, int n_in,
                              void* d_out, int out_size) {
    const int* input = (const int*)d_in[0];
    const float* embed = (const float*)d_in[1];
    const float* w_ih = (const float*)d_in[2];
    const float* w_hh = (const float*)d_in[3];
    const float* b_ih = (const float*)d_in[4];
    const float* b_hh = (const float*)d_in[5];
    float* out = (float*)d_out;

    cudaFuncSetAttribute(lstm_step, cudaFuncAttributeMaxDynamicSharedMemorySize,
                         SMEM_TOTAL);

    prep_W<<<NCTA * NKT, 256>>>(w_ih, w_hh);
    prep_X<<<T_DIM * 5, 256>>>(input, embed);
    prep_init<<<1024, 256>>>(b_ih, b_hh);

    for (int t = 0; t < T_DIM; t++) {
        lstm_step<<<NCTA, 256, SMEM_TOTAL>>>(t, out);
    }
}

// round 10
// speedup vs baseline: 10.9042x; 1.0264x over previous
#include <cuda_runtime.h>
#include <cuda_fp16.h>
#include <cstdint>
#include <math.h>

// ---------------- problem dims ----------------
#define B_DIM 128
#define T_DIM 64
#define E_DIM 300
#define H_DIM 2048
#define NCTA  128          // each CTA owns 16 H-cols x 4 gates = N=64 output cols
#define NKT   37           // K tiles of 64: 32 (h part) + 5 (x part, 320 padded)
#define KTH   32
#define A_TILE 16384       // A: 128 rows x 128B, SW128
#define W_TILE 8192        // W: 64 rows x 128B, SW128
#define STAGE_BYTES (A_TILE + W_TILE)   // 24576
#define NS 8
#define SC_OFF (NS * STAGE_BYTES)       // 196608
#define SMEM_TOTAL (SC_OFF + 512)
#define NTHR 512

// ---------------- device scratch ----------------
__device__ __align__(128) uint8_t g_W[(size_t)NCTA * NKT * W_TILE];   // ~37.9 MB
__device__ __align__(128) uint8_t g_A[2][(size_t)KTH * A_TILE];       // 2 x 512 KB
__device__ __align__(128) uint8_t g_X[T_DIM][(size_t)5 * A_TILE];     // 5 MB
__device__ float g_c[B_DIM * H_DIM];
__device__ float g_bsum[4 * H_DIM];

// ---------------- PTX helpers ----------------
__device__ __forceinline__ uint32_t s2u(const void* p) {
    uint32_t a;
    asm("{ .reg .u64 t; cvta.to.shared.u64 t, %1; cvt.u32.u64 %0, t; }"
        : "=r"(a) : "l"(p));
    return a;
}

__device__ __forceinline__ void mbar_init(uint32_t a, uint32_t cnt) {
    asm volatile("mbarrier.init.shared.b64 [%0], %1;" :: "r"(a), "r"(cnt) : "memory");
}
__device__ __forceinline__ void mbar_arrive(uint32_t a) {
    asm volatile("mbarrier.arrive.shared.b64 _, [%0];" :: "r"(a) : "memory");
}
__device__ __forceinline__ void mbar_expect_tx(uint32_t a, uint32_t bytes) {
    asm volatile("mbarrier.arrive.expect_tx.shared.b64 _, [%0], %1;"
                 :: "r"(a), "r"(bytes) : "memory");
}
__device__ __forceinline__ void mbar_wait(uint32_t a, uint32_t par) {
    asm volatile(
        "{\n\t.reg .pred P;\n\t"
        "W%=:\n\t"
        "mbarrier.try_wait.parity.acquire.cta.shared::cta.b64 P, [%0], %1, 0x989680;\n\t"
        "@P bra D%=;\n\t"
        "bra W%=;\n\t"
        "D%=:\n\t}" :: "r"(a), "r"(par) : "memory");
}

__device__ __forceinline__ void bulk_g2s(uint32_t dst, const void* src,
                                         uint32_t bytes, uint32_t mbar) {
    asm volatile(
        "cp.async.bulk.shared::cluster.global.mbarrier::complete_tx::bytes "
        "[%0], [%1], %2, [%3];"
        :: "r"(dst), "l"(src), "r"(bytes), "r"(mbar) : "memory");
}

__device__ __forceinline__ void ldsm4(uint32_t a[4], uint32_t addr) {
    asm volatile("ldmatrix.sync.aligned.m8n8.x4.shared.b16 {%0,%1,%2,%3}, [%4];"
                 : "=r"(a[0]), "=r"(a[1]), "=r"(a[2]), "=r"(a[3]) : "r"(addr));
}

__device__ __forceinline__ void mma16816(float c[4], const uint32_t a[4],
                                         uint32_t b0, uint32_t b1) {
    asm volatile(
        "mma.sync.aligned.m16n8k16.row.col.f32.f16.f16.f32 "
        "{%0,%1,%2,%3}, {%4,%5,%6,%7}, {%8,%9}, {%0,%1,%2,%3};"
        : "+f"(c[0]), "+f"(c[1]), "+f"(c[2]), "+f"(c[3])
        : "r"(a[0]), "r"(a[1]), "r"(a[2]), "r"(a[3]), "r"(b0), "r"(b1));
}

__device__ __forceinline__ uint32_t swz(uint32_t off) {
    return off ^ ((off >> 3) & 0x70);
}

// ---------------- prep kernels ----------------
__global__ void prep_W(const float* __restrict__ w_ih,
                       const float* __restrict__ w_hh) {
    int j = blockIdx.x / NKT;
    int kt = blockIdx.x % NKT;
    uint8_t* base = g_W + ((size_t)(j * NKT + kt)) * W_TILE;
    for (int idx = threadIdx.x; idx < 64 * 64; idx += blockDim.x) {
        int r = idx >> 6, c = idx & 63;
        int g = r >> 4;
        int wr = g * H_DIM + j * 16 + (r & 15);
        float v = 0.f;
        if (kt < KTH) {
            v = w_hh[(size_t)wr * H_DIM + kt * 64 + c];
        } else {
            int ke = (kt - KTH) * 64 + c;
            if (ke < E_DIM) v = w_ih[(size_t)wr * E_DIM + ke];
        }
        uint32_t sw = swz((uint32_t)(r * 128 + c * 2));
        *(__half*)(base + sw) = __float2half_rn(v);
    }
}

__global__ void prep_X(const int* __restrict__ input,
                       const float* __restrict__ embed) {
    int t = blockIdx.x / 5;
    int kt = blockIdx.x % 5;
    uint8_t* base = g_X[t] + (size_t)kt * A_TILE;
    for (int idx = threadIdx.x; idx < 128 * 64; idx += blockDim.x) {
        int row = idx >> 6, c = idx & 63;
        int ke = kt * 64 + c;
        float v = 0.f;
        if (ke < E_DIM) {
            int tok = input[row * T_DIM + t];
            v = embed[(size_t)tok * E_DIM + ke];
        }
        uint32_t sw = swz((uint32_t)(row * 128 + c * 2));
        *(__half*)(base + sw) = __float2half_rn(v);
    }
}

__global__ void prep_init(const float* __restrict__ b_ih,
                          const float* __restrict__ b_hh) {
    int i = blockIdx.x * blockDim.x + threadIdx.x;
    if (i < 131072) ((uint32_t*)g_A[0])[i] = 0u;   // h(0) fp16 tiles = 0
    if (i < 262144) g_c[i] = 0.f;
    if (i < 4 * H_DIM) g_bsum[i] = b_ih[i] + b_hh[i];
}

// ---------------- step kernel ----------------
__global__ __launch_bounds__(NTHR, 1) void lstm_step(int t, float* __restrict__ out) {
    extern __shared__ __align__(1024) uint8_t smem[];
    const uint32_t sbase = s2u(smem);
    const int tid = threadIdx.x;
    const int lane = tid & 31;
    const int wid = tid >> 5;
    const int warp_m = wid & 3;   // m0 = warp_m*32
    const int warp_n = wid >> 2;  // n0 = warp_n*16 (0..3)
    const int j0 = blockIdx.x * 16;

    const uint32_t full0 = sbase + SC_OFF;        // full[8]
    const uint32_t done0 = sbase + SC_OFF + 64;   // done[8], count=16
    float* sb = (float*)(smem + SC_OFF + 128);

    if (tid == 0) {
        for (int s = 0; s < NS; s++) {
            mbar_init(full0 + 8 * s, 1);
            mbar_init(done0 + 8 * s, 16);
        }
    }
    if (tid >= 64 && tid < 128) {
        int i = tid - 64;
        sb[i] = g_bsum[(i >> 4) * H_DIM + j0 + (i & 15)];
    }
    __syncthreads();

    const uint8_t* abuf = g_A[t & 1];
    const uint8_t* xbuf = g_X[t];
    const uint8_t* wbuf = g_W + (size_t)blockIdx.x * NKT * W_TILE;

    auto fill = [&](int c) {
        uint32_t stg = sbase + (uint32_t)(c & (NS - 1)) * STAGE_BYTES;
        uint32_t fb = full0 + 8 * (c & (NS - 1));
        mbar_expect_tx(fb, STAGE_BYTES);
        const uint8_t* asrc = (c < KTH) ? (abuf + (size_t)c * A_TILE)
                                        : (xbuf + (size_t)(c - KTH) * A_TILE);
        bulk_g2s(stg, asrc, A_TILE, fb);
        bulk_g2s(stg + A_TILE, wbuf + (size_t)c * W_TILE, W_TILE, fb);
    };

    if (tid == 0) {
#pragma unroll
        for (int c = 0; c < NS; c++) fill(c);
    }

    // per-lane ldmatrix offset components
    const int r8 = lane & 7;
    const int ii = lane >> 3;
    const int a_row = warp_m * 32 + (ii & 1) * 8 + r8;   // + mt*16
    const int a_cb = (ii >> 1) * 16;                     // + kt*32
    const int w_row = warp_n * 16 + (ii >> 1) * 8 + r8;
    const int w_cb = (ii & 1) * 16;                      // + kt*32

    float acc[2][2][4];
#pragma unroll
    for (int mt = 0; mt < 2; mt++)
#pragma unroll
        for (int p = 0; p < 2; p++)
#pragma unroll
            for (int q = 0; q < 4; q++) acc[mt][p][q] = 0.f;

    for (int c = 0; c < NKT; c++) {
        int s = c & (NS - 1);
        uint32_t stg = sbase + (uint32_t)s * STAGE_BYTES;
        mbar_wait(full0 + 8 * s, (c >> 3) & 1);
#pragma unroll
        for (int kt = 0; kt < 4; kt++) {
            uint32_t aH[2][4], wH[4];
#pragma unroll
            for (int mt = 0; mt < 2; mt++) {
                uint32_t sw = swz((uint32_t)((a_row + mt * 16) * 128 + a_cb + kt * 32));
                ldsm4(aH[mt], stg + sw);
            }
            {
                uint32_t sw = swz((uint32_t)(w_row * 128 + w_cb + kt * 32));
                ldsm4(wH, stg + A_TILE + sw);
            }
#pragma unroll
            for (int mt = 0; mt < 2; mt++) {
#pragma unroll
                for (int p = 0; p < 2; p++) {
                    mma16816(acc[mt][p], aH[mt], wH[2 * p], wH[2 * p + 1]);
                }
            }
        }
        if (lane == 0) mbar_arrive(done0 + 8 * s);
        if (tid == 0 && c + NS < NKT) {
            mbar_wait(done0 + 8 * s, (c >> 3) & 1);
            fill(c + NS);
        }
    }
    __syncthreads();

    // gates to smem (reuse stage area), stride 68 to dodge bank conflicts
    float* sg = (float*)smem;
#pragma unroll
    for (int mt = 0; mt < 2; mt++) {
        int mrow = warp_m * 32 + mt * 16 + (lane >> 2);
#pragma unroll
        for (int p = 0; p < 2; p++) {
            int ncol = warp_n * 16 + p * 8 + (lane & 3) * 2;
            sg[mrow * 68 + ncol] = acc[mt][p][0];
            sg[mrow * 68 + ncol + 1] = acc[mt][p][1];
            sg[(mrow + 8) * 68 + ncol] = acc[mt][p][2];
            sg[(mrow + 8) * 68 + ncol + 1] = acc[mt][p][3];
        }
    }
    __syncthreads();

    // LSTM cell: 512 threads x 4 iterations cover 128x16
    const int ktile = j0 >> 6;
    const int cbase = j0 & 63;
    uint8_t* adst = g_A[(t + 1) & 1] + (size_t)ktile * A_TILE;
#pragma unroll
    for (int i = 0; i < 4; i++) {
        int m = (tid >> 4) + i * 32;
        int cc = tid & 15;
        int gi = m * 68 + cc;
        float xi = sg[gi] + sb[cc];
        float xf = sg[gi + 16] + sb[16 + cc];
        float xg = sg[gi + 32] + sb[32 + cc];
        float xo = sg[gi + 48] + sb[48 + cc];
        float ig = 1.f / (1.f + __expf(-xi));
        float fg = 1.f / (1.f + __expf(-xf));
        float gg = 2.f / (1.f + __expf(-2.f * xg)) - 1.f;
        float og = 1.f / (1.f + __expf(-xo));
        int co = m * H_DIM + j0 + cc;
        float cn = fg * g_c[co] + ig * gg;
        g_c[co] = cn;
        float hv = og * (2.f / (1.f + __expf(-2.f * cn)) - 1.f);
        if (t < T_DIM - 1) {
            uint32_t sw = swz((uint32_t)(m * 128 + (cbase + cc) * 2));
            *(__half*)(adst + sw) = __float2half_rn(hv);
        } else {
            out[m * H_DIM + j0 + cc] = hv;
        }
    }
}

// ---------------- host ----------------
extern "C" void kernel_launch(void* const* d_in, const int* in_sizes, int n_in,
                              void* d_out, int out_size) {
    const int* input = (const int*)d_in[0];
    const float* embed = (const float*)d_in[1];
    const float* w_ih = (const float*)d_in[2];
    const float* w_hh = (const float*)d_in[3];
    const float* b_ih = (const float*)d_in[4];
    const float* b_hh = (const float*)d_in[5];
    float* out = (float*)d_out;

    cudaFuncSetAttribute(lstm_step, cudaFuncAttributeMaxDynamicSharedMemorySize,
                         SMEM_TOTAL);

    prep_W<<<NCTA * NKT, 256>>>(w_ih, w_hh);
    prep_X<<<T_DIM * 5, 256>>>(input, embed);
    prep_init<<<1024, 256>>>(b_ih, b_hh);

    for (int t = 0; t < T_DIM; t++) {
        lstm_step<<<NCTA, NTHR, SMEM_TOTAL>>>(t, out);
    }
}

// round 12
// speedup vs baseline: 11.9861x; 1.0992x over previous
#include <cuda_runtime.h>
#include <cuda_fp16.h>
#include <cstdint>
#include <math.h>

// ---------------- problem dims ----------------
#define B_DIM 128
#define T_DIM 64
#define E_DIM 300
#define H_DIM 2048
#define NCTA  128          // each CTA owns 16 H-cols x 4 gates = N=64 output cols
#define NKT   37           // K tiles of 64: 32 (h part) + 5 (x part, 320 padded)
#define KTH   32
#define NC0   18           // chunks for warp-set 0
#define NC1   19           // chunks for warp-set 1
#define A_TILE 16384       // A: 128 rows x 128B, SW128
#define W_TILE 8192        // W: 64 rows x 128B, SW128
#define STAGE_BYTES (A_TILE + W_TILE)   // 24576
#define RING_OFF (4 * STAGE_BYTES)      // 98304 (ring1 base)
#define SC_OFF (8 * STAGE_BYTES)        // 196608
#define SMEM_TOTAL (SC_OFF + 512)
#define NTHR 512

// ---------------- device scratch ----------------
__device__ __align__(128) uint8_t g_W[(size_t)NCTA * NKT * W_TILE];   // ~37.9 MB
__device__ __align__(128) uint8_t g_A[2][(size_t)KTH * A_TILE];       // 2 x 512 KB
__device__ __align__(128) uint8_t g_X[T_DIM][(size_t)5 * A_TILE];     // 5 MB
__device__ float g_c[B_DIM * H_DIM];
__device__ float g_bsum[4 * H_DIM];

// ---------------- PTX helpers ----------------
__device__ __forceinline__ uint32_t s2u(const void* p) {
    uint32_t a;
    asm("{ .reg .u64 t; cvta.to.shared.u64 t, %1; cvt.u32.u64 %0, t; }"
        : "=r"(a) : "l"(p));
    return a;
}

__device__ __forceinline__ void mbar_init(uint32_t a, uint32_t cnt) {
    asm volatile("mbarrier.init.shared.b64 [%0], %1;" :: "r"(a), "r"(cnt) : "memory");
}
__device__ __forceinline__ void mbar_arrive(uint32_t a) {
    asm volatile("mbarrier.arrive.shared.b64 _, [%0];" :: "r"(a) : "memory");
}
__device__ __forceinline__ void mbar_expect_tx(uint32_t a, uint32_t bytes) {
    asm volatile("mbarrier.arrive.expect_tx.shared.b64 _, [%0], %1;"
                 :: "r"(a), "r"(bytes) : "memory");
}
__device__ __forceinline__ void mbar_wait(uint32_t a, uint32_t par) {
    asm volatile(
        "{\n\t.reg .pred P;\n\t"
        "W%=:\n\t"
        "mbarrier.try_wait.parity.acquire.cta.shared::cta.b64 P, [%0], %1, 0x989680;\n\t"
        "@P bra D%=;\n\t"
        "bra W%=;\n\t"
        "D%=:\n\t}" :: "r"(a), "r"(par) : "memory");
}

__device__ __forceinline__ void bulk_g2s(uint32_t dst, const void* src,
                                         uint32_t bytes, uint32_t mbar) {
    asm volatile(
        "cp.async.bulk.shared::cluster.global.mbarrier::complete_tx::bytes "
        "[%0], [%1], %2, [%3];"
        :: "r"(dst), "l"(src), "r"(bytes), "r"(mbar) : "memory");
}

__device__ __forceinline__ void ldsm4(uint32_t a[4], uint32_t addr) {
    asm volatile("ldmatrix.sync.aligned.m8n8.x4.shared.b16 {%0,%1,%2,%3}, [%4];"
                 : "=r"(a[0]), "=r"(a[1]), "=r"(a[2]), "=r"(a[3]) : "r"(addr));
}

__device__ __forceinline__ void mma16816(float c[4], const uint32_t a[4],
                                         uint32_t b0, uint32_t b1) {
    asm volatile(
        "mma.sync.aligned.m16n8k16.row.col.f32.f16.f16.f32 "
        "{%0,%1,%2,%3}, {%4,%5,%6,%7}, {%8,%9}, {%0,%1,%2,%3};"
        : "+f"(c[0]), "+f"(c[1]), "+f"(c[2]), "+f"(c[3])
        : "r"(a[0]), "r"(a[1]), "r"(a[2]), "r"(a[3]), "r"(b0), "r"(b1));
}

__device__ __forceinline__ uint32_t swz(uint32_t off) {
    return off ^ ((off >> 3) & 0x70);
}

// ---------------- prep kernels ----------------
__global__ void prep_W(const float* __restrict__ w_ih,
                       const float* __restrict__ w_hh) {
    int j = blockIdx.x / NKT;
    int kt = blockIdx.x % NKT;
    uint8_t* base = g_W + ((size_t)(j * NKT + kt)) * W_TILE;
    for (int idx = threadIdx.x; idx < 64 * 64; idx += blockDim.x) {
        int r = idx >> 6, c = idx & 63;
        int g = r >> 4;
        int wr = g * H_DIM + j * 16 + (r & 15);
        float v = 0.f;
        if (kt < KTH) {
            v = w_hh[(size_t)wr * H_DIM + kt * 64 + c];
        } else {
            int ke = (kt - KTH) * 64 + c;
            if (ke < E_DIM) v = w_ih[(size_t)wr * E_DIM + ke];
        }
        uint32_t sw = swz((uint32_t)(r * 128 + c * 2));
        *(__half*)(base + sw) = __float2half_rn(v);
    }
}

__global__ void prep_X(const int* __restrict__ input,
                       const float* __restrict__ embed) {
    int t = blockIdx.x / 5;
    int kt = blockIdx.x % 5;
    uint8_t* base = g_X[t] + (size_t)kt * A_TILE;
    for (int idx = threadIdx.x; idx < 128 * 64; idx += blockDim.x) {
        int row = idx >> 6, c = idx & 63;
        int ke = kt * 64 + c;
        float v = 0.f;
        if (ke < E_DIM) {
            int tok = input[row * T_DIM + t];
            v = embed[(size_t)tok * E_DIM + ke];
        }
        uint32_t sw = swz((uint32_t)(row * 128 + c * 2));
        *(__half*)(base + sw) = __float2half_rn(v);
    }
}

__global__ void prep_init(const float* __restrict__ b_ih,
                          const float* __restrict__ b_hh) {
    int i = blockIdx.x * blockDim.x + threadIdx.x;
    if (i < 131072) ((uint32_t*)g_A[0])[i] = 0u;   // h(0) fp16 tiles = 0
    if (i < 262144) g_c[i] = 0.f;
    if (i < 4 * H_DIM) g_bsum[i] = b_ih[i] + b_hh[i];
}

// ---------------- step kernel ----------------
// 16 warps = 2 K-sets x 8 warps. Set s owns chunks [s?18:0, s?37:18).
// Within a set: warp tile M64 x N16 (warp_m in 0..1, warp_n in 0..3).
// Each set has its own 4-deep stage ring + producer thread.
__global__ __launch_bounds__(NTHR, 1) void lstm_step(int t, float* __restrict__ out) {
    extern __shared__ __align__(1024) uint8_t smem[];
    const uint32_t sbase = s2u(smem);
    const int tid = threadIdx.x;
    const int lane = tid & 31;
    const int wid = tid >> 5;
    const int set = wid >> 3;      // 0 or 1
    const int lw = wid & 7;        // warp id within set
    const int warp_m = lw & 1;     // m0 = warp_m*64
    const int warp_n = lw >> 1;    // n0 = warp_n*16
    const int j0 = blockIdx.x * 16;

    const uint32_t full0 = sbase + SC_OFF;        // full[8] (ring*4 + stage)
    const uint32_t done0 = sbase + SC_OFF + 64;   // done[8], count=8
    float* sb = (float*)(smem + SC_OFF + 128);

    if (tid == 0) {
        for (int s = 0; s < 8; s++) {
            mbar_init(full0 + 8 * s, 1);
            mbar_init(done0 + 8 * s, 8);
        }
    }
    if (tid >= 64 && tid < 128) {
        int i = tid - 64;
        sb[i] = g_bsum[(i >> 4) * H_DIM + j0 + (i & 15)];
    }
    __syncthreads();

    const uint8_t* abuf = g_A[t & 1];
    const uint8_t* xbuf = g_X[t];
    const uint8_t* wbuf = g_W + (size_t)blockIdx.x * NKT * W_TILE;

    const int nc = set ? NC1 : NC0;       // chunks in my set
    const int c0 = set ? NC0 : 0;         // first global chunk
    const uint32_t ringb = sbase + (uint32_t)set * RING_OFF;
    const uint32_t fullr = full0 + 32 * set;
    const uint32_t doner = done0 + 32 * set;

    // fill local chunk l (global chunk c0+l) into ring stage l&3
    auto fill = [&](int l) {
        int c = c0 + l;
        uint32_t stg = ringb + (uint32_t)(l & 3) * STAGE_BYTES;
        uint32_t fb = fullr + 8 * (l & 3);
        mbar_expect_tx(fb, STAGE_BYTES);
        const uint8_t* asrc = (c < KTH) ? (abuf + (size_t)c * A_TILE)
                                        : (xbuf + (size_t)(c - KTH) * A_TILE);
        bulk_g2s(stg, asrc, A_TILE, fb);
        bulk_g2s(stg + A_TILE, wbuf + (size_t)c * W_TILE, W_TILE, fb);
    };

    const bool prod = (lane == 0) && (lw == 0);   // tid 0 and tid 256
    if (prod) {
#pragma unroll
        for (int l = 0; l < 4; l++) fill(l);
    }

    // per-lane ldmatrix offset components
    const int r8 = lane & 7;
    const int ii = lane >> 3;
    const int a_row = warp_m * 64 + (ii & 1) * 8 + r8;   // + mt*16
    const int a_cb = (ii >> 1) * 16;                     // + kt*32 (bytes)
    const int w_row = warp_n * 16 + (ii >> 1) * 8 + r8;
    const int w_cb = (ii & 1) * 16;                      // + kt*32 (bytes)

    float acc[4][2][4];
#pragma unroll
    for (int mt = 0; mt < 4; mt++)
#pragma unroll
        for (int p = 0; p < 2; p++)
#pragma unroll
            for (int q = 0; q < 4; q++) acc[mt][p][q] = 0.f;

    for (int l = 0; l < nc; l++) {
        int s = l & 3;
        uint32_t stg = ringb + (uint32_t)s * STAGE_BYTES;
        mbar_wait(fullr + 8 * s, (l >> 2) & 1);
#pragma unroll
        for (int kt = 0; kt < 4; kt++) {
            uint32_t aH[4][4], wH[4];
            {
                uint32_t sw = swz((uint32_t)(w_row * 128 + w_cb + kt * 32));
                ldsm4(wH, stg + A_TILE + sw);
            }
#pragma unroll
            for (int mt = 0; mt < 4; mt++) {
                uint32_t sw = swz((uint32_t)((a_row + mt * 16) * 128 + a_cb + kt * 32));
                ldsm4(aH[mt], stg + sw);
            }
#pragma unroll
            for (int mt = 0; mt < 4; mt++) {
#pragma unroll
                for (int p = 0; p < 2; p++) {
                    mma16816(acc[mt][p], aH[mt], wH[2 * p], wH[2 * p + 1]);
                }
            }
        }
        if (lane == 0) mbar_arrive(doner + 8 * s);
        if (prod && l + 4 < nc) {
            mbar_wait(doner + 8 * s, (l >> 2) & 1);
            fill(l + 4);
        }
    }
    __syncthreads();

    // partial gates to smem: set0 -> sg0, set1 -> sg1 (stride 68 vs banks)
    float* sgS = (float*)smem + set * (B_DIM * 68);
#pragma unroll
    for (int mt = 0; mt < 4; mt++) {
        int mrow = warp_m * 64 + mt * 16 + (lane >> 2);
#pragma unroll
        for (int p = 0; p < 2; p++) {
            int ncol = warp_n * 16 + p * 8 + (lane & 3) * 2;
            sgS[mrow * 68 + ncol] = acc[mt][p][0];
            sgS[mrow * 68 + ncol + 1] = acc[mt][p][1];
            sgS[(mrow + 8) * 68 + ncol] = acc[mt][p][2];
            sgS[(mrow + 8) * 68 + ncol + 1] = acc[mt][p][3];
        }
    }
    __syncthreads();

    // LSTM cell: combine the two K-partials + bias; 512 threads x 4 iters
    float* sg0 = (float*)smem;
    float* sg1 = (float*)smem + B_DIM * 68;
    const int ktile = j0 >> 6;
    const int cbase = j0 & 63;
    uint8_t* adst = g_A[(t + 1) & 1] + (size_t)ktile * A_TILE;
#pragma unroll
    for (int i = 0; i < 4; i++) {
        int m = (tid >> 4) + i * 32;
        int cc = tid & 15;
        int gi = m * 68 + cc;
        float xi = sg0[gi] + sg1[gi] + sb[cc];
        float xf = sg0[gi + 16] + sg1[gi + 16] + sb[16 + cc];
        float xg = sg0[gi + 32] + sg1[gi + 32] + sb[32 + cc];
        float xo = sg0[gi + 48] + sg1[gi + 48] + sb[48 + cc];
        float ig = 1.f / (1.f + __expf(-xi));
        float fg = 1.f / (1.f + __expf(-xf));
        float gg = 2.f / (1.f + __expf(-2.f * xg)) - 1.f;
        float og = 1.f / (1.f + __expf(-xo));
        int co = m * H_DIM + j0 + cc;
        float cn = fg * g_c[co] + ig * gg;
        g_c[co] = cn;
        float hv = og * (2.f / (1.f + __expf(-2.f * cn)) - 1.f);
        if (t < T_DIM - 1) {
            uint32_t sw = swz((uint32_t)(m * 128 + (cbase + cc) * 2));
            *(__half*)(adst + sw) = __float2half_rn(hv);
        } else {
            out[m * H_DIM + j0 + cc] = hv;
        }
    }
}

// ---------------- host ----------------
extern "C" void kernel_launch(void* const* d_in, const int* in_sizes, int n_in,
                              void* d_out, int out_size) {
    const int* input = (const int*)d_in[0];
    const float* embed = (const float*)d_in[1];
    const float* w_ih = (const float*)d_in[2];
    const float* w_hh = (const float*)d_in[3];
    const float* b_ih = (const float*)d_in[4];
    const float* b_hh = (const float*)d_in[5];
    float* out = (float*)d_out;

    cudaFuncSetAttribute(lstm_step, cudaFuncAttributeMaxDynamicSharedMemorySize,
                         SMEM_TOTAL);

    prep_W<<<NCTA * NKT, 256>>>(w_ih, w_hh);
    prep_X<<<T_DIM * 5, 256>>>(input, embed);
    prep_init<<<1024, 256>>>(b_ih, b_hh);

    for (int t = 0; t < T_DIM; t++) {
        lstm_step<<<NCTA, NTHR, SMEM_TOTAL>>>(t, out);
    }
}

// round 13
// speedup vs baseline: 12.5836x; 1.0499x over previous
#include <cuda_runtime.h>
#include <cuda_fp16.h>
#include <cstdint>
#include <math.h>

// ---------------- problem dims ----------------
#define B_DIM 128
#define T_DIM 64
#define E_DIM 300
#define H_DIM 2048
#define NCTA  128          // each CTA owns 16 H-cols x 4 gates = N=64 output cols
#define NKT   37           // K tiles of 64: 32 (h part) + 5 (x part, 320 padded)
#define KTH   32
#define A_TILE 16384       // A: 128 rows x 128B, SW128
#define W_TILE 8192        // W: 64 rows x 128B, SW128
#define STAGE_BYTES (A_TILE + W_TILE)   // 24576
#define RING_BYTES (2 * STAGE_BYTES)    // depth-2 ring per set
#define SC_OFF (8 * STAGE_BYTES)        // 196608 (4 rings x 2 stages)
#define SMEM_TOTAL (SC_OFF + 512)
#define NTHR 512

// ---------------- device scratch ----------------
__device__ __align__(128) uint8_t g_W[(size_t)NCTA * NKT * W_TILE];   // ~37.9 MB
__device__ __align__(128) uint8_t g_A[2][(size_t)KTH * A_TILE];       // 2 x 512 KB
__device__ __align__(128) uint8_t g_X[T_DIM][(size_t)5 * A_TILE];     // 5 MB
__device__ float g_c[B_DIM * H_DIM];
__device__ float g_bsum[4 * H_DIM];

// ---------------- PTX helpers ----------------
__device__ __forceinline__ uint32_t s2u(const void* p) {
    uint32_t a;
    asm("{ .reg .u64 t; cvta.to.shared.u64 t, %1; cvt.u32.u64 %0, t; }"
        : "=r"(a) : "l"(p));
    return a;
}

__device__ __forceinline__ void mbar_init(uint32_t a, uint32_t cnt) {
    asm volatile("mbarrier.init.shared.b64 [%0], %1;" :: "r"(a), "r"(cnt) : "memory");
}
__device__ __forceinline__ void mbar_arrive(uint32_t a) {
    asm volatile("mbarrier.arrive.shared.b64 _, [%0];" :: "r"(a) : "memory");
}
__device__ __forceinline__ void mbar_expect_tx(uint32_t a, uint32_t bytes) {
    asm volatile("mbarrier.arrive.expect_tx.shared.b64 _, [%0], %1;"
                 :: "r"(a), "r"(bytes) : "memory");
}
__device__ __forceinline__ void mbar_wait(uint32_t a, uint32_t par) {
    asm volatile(
        "{\n\t.reg .pred P;\n\t"
        "W%=:\n\t"
        "mbarrier.try_wait.parity.acquire.cta.shared::cta.b64 P, [%0], %1, 0x989680;\n\t"
        "@P bra D%=;\n\t"
        "bra W%=;\n\t"
        "D%=:\n\t}" :: "r"(a), "r"(par) : "memory");
}

__device__ __forceinline__ void bulk_g2s(uint32_t dst, const void* src,
                                         uint32_t bytes, uint32_t mbar) {
    asm volatile(
        "cp.async.bulk.shared::cluster.global.mbarrier::complete_tx::bytes "
        "[%0], [%1], %2, [%3];"
        :: "r"(dst), "l"(src), "r"(bytes), "r"(mbar) : "memory");
}

__device__ __forceinline__ void ldsm4(uint32_t a[4], uint32_t addr) {
    asm volatile("ldmatrix.sync.aligned.m8n8.x4.shared.b16 {%0,%1,%2,%3}, [%4];"
                 : "=r"(a[0]), "=r"(a[1]), "=r"(a[2]), "=r"(a[3]) : "r"(addr));
}

__device__ __forceinline__ void mma16816(float c[4], const uint32_t a[4],
                                         uint32_t b0, uint32_t b1) {
    asm volatile(
        "mma.sync.aligned.m16n8k16.row.col.f32.f16.f16.f32 "
        "{%0,%1,%2,%3}, {%4,%5,%6,%7}, {%8,%9}, {%0,%1,%2,%3};"
        : "+f"(c[0]), "+f"(c[1]), "+f"(c[2]), "+f"(c[3])
        : "r"(a[0]), "r"(a[1]), "r"(a[2]), "r"(a[3]), "r"(b0), "r"(b1));
}

__device__ __forceinline__ uint32_t swz(uint32_t off) {
    return off ^ ((off >> 3) & 0x70);
}

// ---------------- prep kernels ----------------
__global__ void prep_W(const float* __restrict__ w_ih,
                       const float* __restrict__ w_hh) {
    int j = blockIdx.x / NKT;
    int kt = blockIdx.x % NKT;
    uint8_t* base = g_W + ((size_t)(j * NKT + kt)) * W_TILE;
    for (int idx = threadIdx.x; idx < 64 * 64; idx += blockDim.x) {
        int r = idx >> 6, c = idx & 63;
        int g = r >> 4;
        int wr = g * H_DIM + j * 16 + (r & 15);
        float v = 0.f;
        if (kt < KTH) {
            v = w_hh[(size_t)wr * H_DIM + kt * 64 + c];
        } else {
            int ke = (kt - KTH) * 64 + c;
            if (ke < E_DIM) v = w_ih[(size_t)wr * E_DIM + ke];
        }
        uint32_t sw = swz((uint32_t)(r * 128 + c * 2));
        *(__half*)(base + sw) = __float2half_rn(v);
    }
}

__global__ void prep_X(const int* __restrict__ input,
                       const float* __restrict__ embed) {
    int t = blockIdx.x / 5;
    int kt = blockIdx.x % 5;
    uint8_t* base = g_X[t] + (size_t)kt * A_TILE;
    for (int idx = threadIdx.x; idx < 128 * 64; idx += blockDim.x) {
        int row = idx >> 6, c = idx & 63;
        int ke = kt * 64 + c;
        float v = 0.f;
        if (ke < E_DIM) {
            int tok = input[row * T_DIM + t];
            v = embed[(size_t)tok * E_DIM + ke];
        }
        uint32_t sw = swz((uint32_t)(row * 128 + c * 2));
        *(__half*)(base + sw) = __float2half_rn(v);
    }
}

__global__ void prep_init(const float* __restrict__ b_ih,
                          const float* __restrict__ b_hh) {
    int i = blockIdx.x * blockDim.x + threadIdx.x;
    if (i < 131072) ((uint32_t*)g_A[0])[i] = 0u;   // h(0) fp16 tiles = 0
    if (i < 262144) g_c[i] = 0.f;
    if (i < 4 * H_DIM) g_bsum[i] = b_ih[i] + b_hh[i];
}

// ---------------- step kernel ----------------
// 16 warps = 4 K-sets x 4 warps. Set s owns ~9-10 of the 37 chunks.
// Within a set: warp tile M64 x N32 (warp_m in 0..1, warp_n in 0..1).
// Each set has its own depth-2 stage ring + producer thread.
__global__ __launch_bounds__(NTHR, 1) void lstm_step(int t, float* __restrict__ out) {
    extern __shared__ __align__(1024) uint8_t smem[];
    const uint32_t sbase = s2u(smem);
    const int tid = threadIdx.x;
    const int lane = tid & 31;
    const int wid = tid >> 5;
    const int set = wid >> 2;      // 0..3
    const int lw = wid & 3;        // warp id within set
    const int warp_m = lw & 1;     // m0 = warp_m*64
    const int warp_n = lw >> 1;    // n0 = warp_n*32
    const int j0 = blockIdx.x * 16;

    const uint32_t full0 = sbase + SC_OFF;        // full[8] = ring*2 + stage
    const uint32_t done0 = sbase + SC_OFF + 64;   // done[8], count=4
    float* sb = (float*)(smem + SC_OFF + 128);

    if (tid == 0) {
        for (int s = 0; s < 8; s++) {
            mbar_init(full0 + 8 * s, 1);
            mbar_init(done0 + 8 * s, 4);
        }
    }
    if (tid >= 64 && tid < 128) {
        int i = tid - 64;
        sb[i] = g_bsum[(i >> 4) * H_DIM + j0 + (i & 15)];
    }
    __syncthreads();

    const uint8_t* abuf = g_A[t & 1];
    const uint8_t* xbuf = g_X[t];
    const uint8_t* wbuf = g_W + (size_t)blockIdx.x * NKT * W_TILE;

    const int c0 = set * 9;                 // sets 0-2: 9 chunks, set 3: 10
    const int nc = 9 + (set == 3 ? 1 : 0);
    const uint32_t ringb = sbase + (uint32_t)set * RING_BYTES;
    const uint32_t fullr = full0 + 16 * set;
    const uint32_t doner = done0 + 16 * set;

    // fill local chunk l (global chunk c0+l) into ring stage l&1
    auto fill = [&](int l) {
        int c = c0 + l;
        uint32_t stg = ringb + (uint32_t)(l & 1) * STAGE_BYTES;
        uint32_t fb = fullr + 8 * (l & 1);
        mbar_expect_tx(fb, STAGE_BYTES);
        const uint8_t* asrc = (c < KTH) ? (abuf + (size_t)c * A_TILE)
                                        : (xbuf + (size_t)(c - KTH) * A_TILE);
        bulk_g2s(stg, asrc, A_TILE, fb);
        bulk_g2s(stg + A_TILE, wbuf + (size_t)c * W_TILE, W_TILE, fb);
    };

    const bool prod = (lane == 0) && (lw == 0);   // one per set
    if (prod) {
        fill(0);
        fill(1);
    }

    // per-lane ldmatrix offset components
    const int r8 = lane & 7;
    const int ii = lane >> 3;
    const int a_row = warp_m * 64 + (ii & 1) * 8 + r8;   // + mt*16
    const int a_cb = (ii >> 1) * 16;                     // + kt*32 (bytes)
    const int w_row = warp_n * 32 + (ii >> 1) * 8 + r8;  // + w*16
    const int w_cb = (ii & 1) * 16;                      // + kt*32 (bytes)

    float acc[4][4][4];   // [mt][p=n8 group][quad]
#pragma unroll
    for (int mt = 0; mt < 4; mt++)
#pragma unroll
        for (int p = 0; p < 4; p++)
#pragma unroll
            for (int q = 0; q < 4; q++) acc[mt][p][q] = 0.f;

    for (int l = 0; l < nc; l++) {
        int s = l & 1;
        uint32_t stg = ringb + (uint32_t)s * STAGE_BYTES;
        mbar_wait(fullr + 8 * s, (l >> 1) & 1);
#pragma unroll
        for (int kt = 0; kt < 4; kt++) {
            uint32_t aH[4][4], wH[2][4];
#pragma unroll
            for (int w = 0; w < 2; w++) {
                uint32_t sw = swz((uint32_t)((w_row + w * 16) * 128 + w_cb + kt * 32));
                ldsm4(wH[w], stg + A_TILE + sw);
            }
#pragma unroll
            for (int mt = 0; mt < 4; mt++) {
                uint32_t sw = swz((uint32_t)((a_row + mt * 16) * 128 + a_cb + kt * 32));
                ldsm4(aH[mt], stg + sw);
            }
#pragma unroll
            for (int mt = 0; mt < 4; mt++) {
#pragma unroll
                for (int w = 0; w < 2; w++) {
#pragma unroll
                    for (int q = 0; q < 2; q++) {
                        mma16816(acc[mt][w * 2 + q], aH[mt],
                                 wH[w][2 * q], wH[w][2 * q + 1]);
                    }
                }
            }
        }
        if (lane == 0) mbar_arrive(doner + 8 * s);
        if (prod && l + 2 < nc) {
            mbar_wait(doner + 8 * s, (l >> 1) & 1);
            fill(l + 2);
        }
    }
    __syncthreads();

    // partial gates to smem: one buffer per set (stride 68 vs banks)
    float* sgS = (float*)smem + set * (B_DIM * 68);
#pragma unroll
    for (int mt = 0; mt < 4; mt++) {
        int mrow = warp_m * 64 + mt * 16 + (lane >> 2);
#pragma unroll
        for (int p = 0; p < 4; p++) {
            int ncol = warp_n * 32 + p * 8 + (lane & 3) * 2;
            sgS[mrow * 68 + ncol] = acc[mt][p][0];
            sgS[mrow * 68 + ncol + 1] = acc[mt][p][1];
            sgS[(mrow + 8) * 68 + ncol] = acc[mt][p][2];
            sgS[(mrow + 8) * 68 + ncol + 1] = acc[mt][p][3];
        }
    }
    __syncthreads();

    // LSTM cell: combine the 4 K-partials + bias; 512 threads x 4 iters
    float* sg0 = (float*)smem;
    float* sg1 = sg0 + B_DIM * 68;
    float* sg2 = sg1 + B_DIM * 68;
    float* sg3 = sg2 + B_DIM * 68;
    const int ktile = j0 >> 6;
    const int cbase = j0 & 63;
    uint8_t* adst = g_A[(t + 1) & 1] + (size_t)ktile * A_TILE;
#pragma unroll
    for (int i = 0; i < 4; i++) {
        int m = (tid >> 4) + i * 32;
        int cc = tid & 15;
        int gi = m * 68 + cc;
        float xi = (sg0[gi] + sg1[gi]) + (sg2[gi] + sg3[gi]) + sb[cc];
        float xf = (sg0[gi + 16] + sg1[gi + 16]) + (sg2[gi + 16] + sg3[gi + 16])
                   + sb[16 + cc];
        float xg = (sg0[gi + 32] + sg1[gi + 32]) + (sg2[gi + 32] + sg3[gi + 32])
                   + sb[32 + cc];
        float xo = (sg0[gi + 48] + sg1[gi + 48]) + (sg2[gi + 48] + sg3[gi + 48])
                   + sb[48 + cc];
        float ig = 1.f / (1.f + __expf(-xi));
        float fg = 1.f / (1.f + __expf(-xf));
        float gg = 2.f / (1.f + __expf(-2.f * xg)) - 1.f;
        float og = 1.f / (1.f + __expf(-xo));
        int co = m * H_DIM + j0 + cc;
        float cn = fg * g_c[co] + ig * gg;
        g_c[co] = cn;
        float hv = og * (2.f / (1.f + __expf(-2.f * cn)) - 1.f);
        if (t < T_DIM - 1) {
            uint32_t sw = swz((uint32_t)(m * 128 + (cbase + cc) * 2));
            *(__half*)(adst + sw) = __float2half_rn(hv);
        } else {
            out[m * H_DIM + j0 + cc] = hv;
        }
    }
}

// ---------------- host ----------------
extern "C" void kernel_launch(void* const* d_in, const int* in_sizes, int n_in,
                              void* d_out, int out_size) {
    const int* input = (const int*)d_in[0];
    const float* embed = (const float*)d_in[1];
    const float* w_ih = (const float*)d_in[2];
    const float* w_hh = (const float*)d_in[3];
    const float* b_ih = (const float*)d_in[4];
    const float* b_hh = (const float*)d_in[5];
    float* out = (float*)d_out;

    cudaFuncSetAttribute(lstm_step, cudaFuncAttributeMaxDynamicSharedMemorySize,
                         SMEM_TOTAL);

    prep_W<<<NCTA * NKT, 256>>>(w_ih, w_hh);
    prep_X<<<T_DIM * 5, 256>>>(input, embed);
    prep_init<<<1024, 256>>>(b_ih, b_hh);

    for (int t = 0; t < T_DIM; t++) {
        lstm_step<<<NCTA, NTHR, SMEM_TOTAL>>>(t, out);
    }
}